// round 4
// baseline (speedup 1.0000x reference)
#include <cuda_runtime.h>
#include <math.h>

#define BATCH 32
#define IMGH 112
#define IMGW 112
#define CC 96
#define NH 3
#define WS 7
#define SHIFT 3
#define NN 49
#define HD 32
#define NWIN 8192
#define TOK 401408
#define HID 384
#define QKVC 288

typedef unsigned long long u64;

__device__ __forceinline__ u64 pk2(float lo, float hi) {
    u64 r; asm("mov.b64 %0,{%1,%2};" : "=l"(r) : "f"(lo), "f"(hi)); return r;
}
__device__ __forceinline__ void up2(u64 v, float& a, float& b) {
    asm("mov.b64 {%0,%1},%2;" : "=f"(a), "=f"(b) : "l"(v));
}
__device__ __forceinline__ void fma2(u64& d, u64 a, u64 b) {
    asm("fma.rn.f32x2 %0,%1,%2,%3;" : "=l"(d) : "l"(a), "l"(b), "l"(d));
}

__device__ float g_x1[(size_t)TOK * CC];   // 154 MB residual scratch

// smem float offsets (fused attention kernel)
#define AT_OFF   0            // sAT/sOT [96][50]   4800
#define QK_OFF   4800         // sQK [49][194]      9506
#define VT_OFF   14306        // sVT [96][50]       4800
#define W_OFF    19106        // sW  [96][97]       9312
#define S_OFF    28418        // sS  [3][49][50]    7350
#define SMEM1_FLOATS 35768
#define QKP 194
#define SP 50

// =====================================================================
// Kernel 1: gather+LN1+QKV+attention+proj+residual (fully fused)
// grid = NWIN, 256 threads
// =====================================================================
__global__ void __launch_bounds__(256) k_attn_fused(
    const float* __restrict__ x,
    const float* __restrict__ attn_mask,
    const int*   __restrict__ rel_index,
    const float* __restrict__ rel_bias_table,
    const float* __restrict__ n1g, const float* __restrict__ n1b,
    const float* __restrict__ qkv_w, const float* __restrict__ qkv_b,
    const float* __restrict__ proj_w, const float* __restrict__ proj_b)
{
    extern __shared__ float sm[];
    float* sAT = sm + AT_OFF;   // [96][50] channel-major LN'd input (later sOT)
    float* sQK = sm + QK_OFF;   // [49][194] Q cols 0..95, K cols 96..191
    float* sVT = sm + VT_OFF;   // [96][50] channel-major V
    float* sW  = sm + W_OFF;    // [96][97]
    float* sS  = sm + S_OFF;    // [3][49][50]

    const int widx = blockIdx.x;
    const int b  = widx >> 8;
    const int wi = widx & 255;
    const int wh = wi >> 4;
    const int ww = wi & 15;
    const int tid  = threadIdx.x;
    const int lane = tid & 31;
    const int warp = tid >> 5;

    // ---- gather (shifted window) + LN1, write transposed [ch][tok] ----
    if (tid < 96) sAT[tid * SP + 49] = 0.f;   // zero pad token slot
    for (int n = warp; n < NN; n += 8) {
        int r = n / WS, cc = n - r * WS;
        int sh = (wh * WS + r + SHIFT) % IMGH;
        int sw = (ww * WS + cc + SHIFT) % IMGW;
        const float* xp = x + (size_t)((b * IMGH + sh) * IMGW + sw) * CC;
        float v0 = xp[lane], v1 = xp[lane + 32], v2 = xp[lane + 64];
        float s = v0 + v1 + v2, s2 = v0 * v0 + v1 * v1 + v2 * v2;
        #pragma unroll
        for (int o = 16; o > 0; o >>= 1) {
            s  += __shfl_xor_sync(0xffffffffu, s, o);
            s2 += __shfl_xor_sync(0xffffffffu, s2, o);
        }
        float m = s * (1.0f / CC);
        float inv = rsqrtf(s2 * (1.0f / CC) - m * m + 1e-5f);
        sAT[lane * SP + n]        = (v0 - m) * inv * n1g[lane]      + n1b[lane];
        sAT[(lane + 32) * SP + n] = (v1 - m) * inv * n1g[lane + 32] + n1b[lane + 32];
        sAT[(lane + 64) * SP + n] = (v2 - m) * inv * n1g[lane + 64] + n1b[lane + 64];
    }
    __syncthreads();

    // ---- QKV GEMM: 3 tiles of 96 output cols ----
    const int c = lane;
    const int g8 = warp;
    for (int ct = 0; ct < 3; ct++) {
        for (int i = tid; i < 96 * 96; i += 256) {
            int cl = i / 96, k = i - cl * 96;
            sW[k * 97 + cl] = qkv_w[(ct * 96 + cl) * 96 + k];
        }
        // hoist biases for this tile
        float bi0 = qkv_b[ct * 96 + c];
        float bi1 = qkv_b[ct * 96 + c + 32];
        float bi2 = qkv_b[ct * 96 + c + 64];
        __syncthreads();

        u64 acc[4][3];
        #pragma unroll
        for (int j = 0; j < 4; j++) { acc[j][0] = acc[j][1] = acc[j][2] = 0ull; }
        const int np = (g8 == 0) ? 4 : 3;   // token pairs: g8, g8+8, g8+16, (24)

        for (int k = 0; k < 96; k++) {
            float b0 = sW[k * 97 + c], b1 = sW[k * 97 + c + 32], b2 = sW[k * 97 + c + 64];
            u64 B0 = pk2(b0, b0), B1 = pk2(b1, b1), B2 = pk2(b2, b2);
            const float* ar = &sAT[k * SP];
            #pragma unroll
            for (int j = 0; j < 3; j++) {
                u64 A = *(const u64*)&ar[2 * (g8 + j * 8)];
                fma2(acc[j][0], A, B0);
                fma2(acc[j][1], A, B1);
                fma2(acc[j][2], A, B2);
            }
            if (g8 == 0) {
                u64 A = *(const u64*)&ar[48];
                fma2(acc[3][0], A, B0);
                fma2(acc[3][1], A, B1);
                fma2(acc[3][2], A, B2);
            }
        }
        // store
        const float biases[3] = { bi0, bi1, bi2 };
        for (int j = 0; j < np; j++) {
            int tp = (j < 3) ? (g8 + j * 8) : 24;
            int n0 = 2 * tp;
            #pragma unroll
            for (int m = 0; m < 3; m++) {
                int col = c + m * 32;
                float lo, hi; up2(acc[j][m], lo, hi);
                lo += biases[m]; hi += biases[m];
                if (ct < 2) {
                    sQK[n0 * QKP + ct * 96 + col] = lo;
                    if (n0 + 1 < NN) sQK[(n0 + 1) * QKP + ct * 96 + col] = hi;
                } else {
                    *(float2*)&sVT[col * SP + n0] = make_float2(lo, hi);
                }
            }
        }
        __syncthreads();
    }

    // ---- scores: QK^T * scale + bias + mask ----
    const float scale = 0.17677669529663689f;
    const float* maskw = attn_mask + (size_t)wi * NN * NN;
    for (int idx = tid; idx < NH * NN * NN; idx += 256) {
        int h = idx / (NN * NN);
        int r = idx - h * NN * NN;
        int i = r / NN, j = r - i * NN;
        const float* qp = &sQK[i * QKP + h * HD];
        const float* kp = &sQK[j * QKP + 96 + h * HD];
        u64 acc = 0ull;
        #pragma unroll
        for (int d = 0; d < 16; d++)
            fma2(acc, *(const u64*)&qp[2 * d], *(const u64*)&kp[2 * d]);
        float a0, a1; up2(acc, a0, a1);
        float s = (a0 + a1) * scale
                + rel_bias_table[rel_index[r] * NH + h]
                + maskw[r];
        sS[(h * NN + i) * SP + j] = s;
    }
    __syncthreads();

    // ---- softmax (warp per row) + zero pad col 49 ----
    for (int row = warp; row < NH * NN; row += 8) {
        float* rp = &sS[row * SP];
        float x0 = (lane < NN) ? rp[lane] : -1e30f;
        float x1 = (lane + 32 < NN) ? rp[lane + 32] : -1e30f;
        float mx = fmaxf(x0, x1);
        #pragma unroll
        for (int o = 16; o > 0; o >>= 1)
            mx = fmaxf(mx, __shfl_xor_sync(0xffffffffu, mx, o));
        float e0 = (lane < NN) ? __expf(x0 - mx) : 0.f;
        float e1 = (lane + 32 < NN) ? __expf(x1 - mx) : 0.f;
        float sum = e0 + e1;
        #pragma unroll
        for (int o = 16; o > 0; o >>= 1)
            sum += __shfl_xor_sync(0xffffffffu, sum, o);
        float inv = 1.0f / sum;
        if (lane < NN) rp[lane] = e0 * inv;
        if (lane + 32 < NN) rp[lane + 32] = e1 * inv;
        if (lane == 0) rp[49] = 0.f;
    }
    __syncthreads();

    // ---- attn @ V  -> sOT (aliases sAT) [col][tok] ----
    float* sOT = sAT;
    for (int idx = tid; idx < CC * NN; idx += 256) {
        int col = idx / NN, i = idx - col * NN;
        int h = col >> 5;
        const float* sp = &sS[(h * NN + i) * SP];
        const float* vp = &sVT[col * SP];
        u64 acc = 0ull;
        #pragma unroll
        for (int jp = 0; jp < 25; jp++)
            fma2(acc, *(const u64*)&sp[2 * jp], *(const u64*)&vp[2 * jp]);
        float a0, a1; up2(acc, a0, a1);
        sOT[col * SP + i] = a0 + a1;
    }
    __syncthreads();

    // ---- proj ----
    for (int i = tid; i < 96 * 96; i += 256) {
        int cl = i / 96, k = i - cl * 96;
        sW[k * 97 + cl] = proj_w[cl * 96 + k];
    }
    // zero pad token for sOT (written above only for i<49)
    if (tid < 96) sOT[tid * SP + 49] = 0.f;
    float pb0 = proj_b[c];
    float pb1 = proj_b[c + 32];
    float pb2 = proj_b[c + 64];
    __syncthreads();

    u64 acc[4][3];
    #pragma unroll
    for (int j = 0; j < 4; j++) { acc[j][0] = acc[j][1] = acc[j][2] = 0ull; }
    const int np = (g8 == 0) ? 4 : 3;
    for (int k = 0; k < 96; k++) {
        float b0 = sW[k * 97 + c], b1 = sW[k * 97 + c + 32], b2 = sW[k * 97 + c + 64];
        u64 B0 = pk2(b0, b0), B1 = pk2(b1, b1), B2 = pk2(b2, b2);
        const float* ar = &sOT[k * SP];
        #pragma unroll
        for (int j = 0; j < 3; j++) {
            u64 A = *(const u64*)&ar[2 * (g8 + j * 8)];
            fma2(acc[j][0], A, B0);
            fma2(acc[j][1], A, B1);
            fma2(acc[j][2], A, B2);
        }
        if (g8 == 0) {
            u64 A = *(const u64*)&ar[48];
            fma2(acc[3][0], A, B0);
            fma2(acc[3][1], A, B1);
            fma2(acc[3][2], A, B2);
        }
    }
    // scatter + residual
    const float pbs[3] = { pb0, pb1, pb2 };
    for (int j = 0; j < np; j++) {
        int tp = (j < 3) ? (g8 + j * 8) : 24;
        #pragma unroll
        for (int half = 0; half < 2; half++) {
            int n = 2 * tp + half;
            if (n >= NN) break;
            int r = n / WS, cc = n - r * WS;
            int sh = (wh * WS + r + SHIFT) % IMGH;
            int sw = (ww * WS + cc + SHIFT) % IMGW;
            size_t base = (size_t)((b * IMGH + sh) * IMGW + sw) * CC;
            #pragma unroll
            for (int m = 0; m < 3; m++) {
                int col = c + m * 32;
                float lo, hi; up2(acc[j][m], lo, hi);
                float v = half ? hi : lo;
                g_x1[base + col] = x[base + col] + v + pbs[m];
            }
        }
    }
}

// =====================================================================
// Kernel 2: LN2 + fc1 + GELU + fc2 + residual (f32x2, transposed acts)
// grid = TOK/64, 256 threads
// =====================================================================
#define XT_OFF 0              // sXT [96][66]   6336
#define HT_OFF 6336           // sHT [384][66]  25344
#define W2_OFF 31680          // sW  [96][97]   9312
#define SMEM2_FLOATS 40992
#define TP 66

__global__ void __launch_bounds__(256) k_mlp(
    const float* __restrict__ n2g, const float* __restrict__ n2b,
    const float* __restrict__ fc1_w, const float* __restrict__ fc1_b,
    const float* __restrict__ fc2_w, const float* __restrict__ fc2_b,
    float* __restrict__ out)
{
    extern __shared__ float sm[];
    float* sXT = sm + XT_OFF;
    float* sHT = sm + HT_OFF;
    float* sW  = sm + W2_OFF;

    const int tid = threadIdx.x;
    const int lane = tid & 31;
    const int warp = tid >> 5;
    const int t0 = blockIdx.x * 64;
    const int c = lane;
    const int g8 = warp;

    // LN2 -> sXT [ch][tok]
    for (int n = warp; n < 64; n += 8) {
        const float* xp = g_x1 + (size_t)(t0 + n) * CC;
        float v0 = xp[lane], v1 = xp[lane + 32], v2 = xp[lane + 64];
        float s = v0 + v1 + v2, s2 = v0 * v0 + v1 * v1 + v2 * v2;
        #pragma unroll
        for (int o = 16; o > 0; o >>= 1) {
            s  += __shfl_xor_sync(0xffffffffu, s, o);
            s2 += __shfl_xor_sync(0xffffffffu, s2, o);
        }
        float m = s * (1.0f / CC);
        float inv = rsqrtf(s2 * (1.0f / CC) - m * m + 1e-5f);
        sXT[lane * TP + n]        = (v0 - m) * inv * n2g[lane]      + n2b[lane];
        sXT[(lane + 32) * TP + n] = (v1 - m) * inv * n2g[lane + 32] + n2b[lane + 32];
        sXT[(lane + 64) * TP + n] = (v2 - m) * inv * n2g[lane + 64] + n2b[lane + 64];
    }
    __syncthreads();

    // fc1 + GELU: 4 tiles of 96 cols; token pairs tp = g8*4 + jj
    for (int ct = 0; ct < 4; ct++) {
        for (int i = tid; i < 96 * 96; i += 256) {
            int cl = i / 96, k = i - cl * 96;
            sW[k * 97 + cl] = fc1_w[(ct * 96 + cl) * 96 + k];
        }
        float bi0 = fc1_b[ct * 96 + c];
        float bi1 = fc1_b[ct * 96 + c + 32];
        float bi2 = fc1_b[ct * 96 + c + 64];
        __syncthreads();

        u64 acc[4][3];
        #pragma unroll
        for (int j = 0; j < 4; j++) { acc[j][0] = acc[j][1] = acc[j][2] = 0ull; }
        for (int k = 0; k < 96; k++) {
            float b0 = sW[k * 97 + c], b1 = sW[k * 97 + c + 32], b2 = sW[k * 97 + c + 64];
            u64 B0 = pk2(b0, b0), B1 = pk2(b1, b1), B2 = pk2(b2, b2);
            const float* ar = &sXT[k * TP];
            #pragma unroll
            for (int j = 0; j < 4; j++) {
                u64 A = *(const u64*)&ar[2 * (g8 * 4 + j)];
                fma2(acc[j][0], A, B0);
                fma2(acc[j][1], A, B1);
                fma2(acc[j][2], A, B2);
            }
        }
        const float biases[3] = { bi0, bi1, bi2 };
        #pragma unroll
        for (int j = 0; j < 4; j++) {
            int n0 = 2 * (g8 * 4 + j);
            #pragma unroll
            for (int m = 0; m < 3; m++) {
                int col = ct * 96 + c + m * 32;
                float lo, hi; up2(acc[j][m], lo, hi);
                lo += biases[m]; hi += biases[m];
                lo = 0.5f * lo * (1.0f + erff(lo * 0.70710678118654752f));
                hi = 0.5f * hi * (1.0f + erff(hi * 0.70710678118654752f));
                *(float2*)&sHT[col * TP + n0] = make_float2(lo, hi);
            }
        }
        __syncthreads();
    }

    // fc2: 96 cols, k = 384 in 4 staged chunks of 96
    u64 acc[4][3];
    #pragma unroll
    for (int j = 0; j < 4; j++) { acc[j][0] = acc[j][1] = acc[j][2] = 0ull; }
    for (int kc = 0; kc < 4; kc++) {
        for (int i = tid; i < 96 * 96; i += 256) {
            int cl = i / 96, kk = i - cl * 96;
            sW[kk * 97 + cl] = fc2_w[cl * HID + kc * 96 + kk];
        }
        __syncthreads();
        for (int kk = 0; kk < 96; kk++) {
            float b0 = sW[kk * 97 + c], b1 = sW[kk * 97 + c + 32], b2 = sW[kk * 97 + c + 64];
            u64 B0 = pk2(b0, b0), B1 = pk2(b1, b1), B2 = pk2(b2, b2);
            const float* ar = &sHT[(kc * 96 + kk) * TP];
            #pragma unroll
            for (int j = 0; j < 4; j++) {
                u64 A = *(const u64*)&ar[2 * (g8 * 4 + j)];
                fma2(acc[j][0], A, B0);
                fma2(acc[j][1], A, B1);
                fma2(acc[j][2], A, B2);
            }
        }
        __syncthreads();
    }
    float fb0 = fc2_b[c], fb1 = fc2_b[c + 32], fb2 = fc2_b[c + 64];
    const float fbs[3] = { fb0, fb1, fb2 };
    #pragma unroll
    for (int j = 0; j < 4; j++) {
        int n0 = 2 * (g8 * 4 + j);
        size_t base0 = (size_t)(t0 + n0) * CC;
        size_t base1 = (size_t)(t0 + n0 + 1) * CC;
        #pragma unroll
        for (int m = 0; m < 3; m++) {
            int col = c + m * 32;
            float lo, hi; up2(acc[j][m], lo, hi);
            out[base0 + col] = g_x1[base0 + col] + lo + fbs[m];
            out[base1 + col] = g_x1[base1 + col] + hi + fbs[m];
        }
    }
}

// =====================================================================
extern "C" void kernel_launch(void* const* d_in, const int* in_sizes, int n_in,
                              void* d_out, int out_size)
{
    const float* x      = (const float*)d_in[0];
    const float* mask   = (const float*)d_in[1];
    const int*   relidx = (const int*)  d_in[2];
    const float* n1g    = (const float*)d_in[3];
    const float* n1b    = (const float*)d_in[4];
    const float* qkv_w  = (const float*)d_in[5];
    const float* qkv_b  = (const float*)d_in[6];
    const float* proj_w = (const float*)d_in[7];
    const float* proj_b = (const float*)d_in[8];
    const float* rbt    = (const float*)d_in[9];
    const float* n2g    = (const float*)d_in[10];
    const float* n2b    = (const float*)d_in[11];
    const float* fc1_w  = (const float*)d_in[12];
    const float* fc1_b  = (const float*)d_in[13];
    const float* fc2_w  = (const float*)d_in[14];
    const float* fc2_b  = (const float*)d_in[15];
    float* out = (float*)d_out;

    const int smem1 = SMEM1_FLOATS * 4;   // 143072
    const int smem2 = SMEM2_FLOATS * 4;   // 163968

    cudaFuncSetAttribute(k_attn_fused, cudaFuncAttributeMaxDynamicSharedMemorySize, smem1);
    cudaFuncSetAttribute(k_mlp,        cudaFuncAttributeMaxDynamicSharedMemorySize, smem2);

    k_attn_fused<<<NWIN, 256, smem1>>>(x, mask, relidx, rbt, n1g, n1b,
                                       qkv_w, qkv_b, proj_w, proj_b);
    k_mlp<<<TOK / 64, 256, smem2>>>(n2g, n2b, fc1_w, fc1_b, fc2_w, fc2_b, out);
}

// round 7
// speedup vs baseline: 1.3824x; 1.3824x over previous
#include <cuda_runtime.h>
#include <math.h>

#define BATCH 32
#define IMGH 112
#define IMGW 112
#define CC 96
#define NH 3
#define WS 7
#define SHIFT 3
#define NN 49
#define HD 32
#define NWIN 8192
#define TOK 401408
#define HID 384
#define QKVC 288

typedef unsigned long long u64;

__device__ __forceinline__ u64 pk2(float lo, float hi) {
    u64 r; asm("mov.b64 %0,{%1,%2};" : "=l"(r) : "f"(lo), "f"(hi)); return r;
}
__device__ __forceinline__ void up2(u64 v, float& a, float& b) {
    asm("mov.b64 {%0,%1},%2;" : "=f"(a), "=f"(b) : "l"(v));
}
__device__ __forceinline__ void fma2(u64& d, u64 a, u64 b) {
    asm("fma.rn.f32x2 %0,%1,%2,%3;" : "=l"(d) : "l"(a), "l"(b), "l"(d));
}

__device__ float g_x1[(size_t)TOK * CC];   // 154 MB residual scratch

// smem float offsets (fused attention kernel) — sW and sS ALIASED
#define AT_OFF   0            // sAT/sOT [96][50]   4800
#define QK_OFF   4800         // sQK [49][194]      9506
#define VT_OFF   14306        // sVT [96][50]       4800
#define WS_OFF   19106        // sW [96][97] / sS [3][49][50]  9312
#define SMEM1_FLOATS 28418    // 113672 B -> 2 CTAs/SM
#define QKP 194
#define SP 50

// =====================================================================
// Kernel 1: gather+LN1+QKV+attention+proj+residual (fully fused)
// grid = NWIN, 256 threads, 2 CTAs/SM
// =====================================================================
__global__ void __launch_bounds__(256) k_attn_fused(
    const float* __restrict__ x,
    const float* __restrict__ attn_mask,
    const int*   __restrict__ rel_index,
    const float* __restrict__ rel_bias_table,
    const float* __restrict__ n1g, const float* __restrict__ n1b,
    const float* __restrict__ qkv_w, const float* __restrict__ qkv_b,
    const float* __restrict__ proj_w, const float* __restrict__ proj_b)
{
    extern __shared__ float sm[];
    float* sAT = sm + AT_OFF;   // [96][50] channel-major LN'd input (later sOT)
    float* sQK = sm + QK_OFF;   // [49][194] Q cols 0..95, K cols 96..191
    float* sVT = sm + VT_OFF;   // [96][50] channel-major V
    float* sW  = sm + WS_OFF;   // [96][97]  (weights)  -- aliased with:
    float* sS  = sm + WS_OFF;   // [3][49][50] (scores)

    const int widx = blockIdx.x;
    const int b  = widx >> 8;
    const int wi = widx & 255;
    const int wh = wi >> 4;
    const int ww = wi & 15;
    const int tid  = threadIdx.x;
    const int lane = tid & 31;
    const int warp = tid >> 5;

    // ---- gather (shifted window) + LN1, write transposed [ch][tok] ----
    if (tid < 96) sAT[tid * SP + 49] = 0.f;   // zero pad token slot
    for (int n = warp; n < NN; n += 8) {
        int r = n / WS, cc = n - r * WS;
        int sh = (wh * WS + r + SHIFT) % IMGH;
        int sw = (ww * WS + cc + SHIFT) % IMGW;
        const float* xp = x + (size_t)((b * IMGH + sh) * IMGW + sw) * CC;
        float v0 = xp[lane], v1 = xp[lane + 32], v2 = xp[lane + 64];
        float s = v0 + v1 + v2, s2 = v0 * v0 + v1 * v1 + v2 * v2;
        #pragma unroll
        for (int o = 16; o > 0; o >>= 1) {
            s  += __shfl_xor_sync(0xffffffffu, s, o);
            s2 += __shfl_xor_sync(0xffffffffu, s2, o);
        }
        float m = s * (1.0f / CC);
        float inv = rsqrtf(s2 * (1.0f / CC) - m * m + 1e-5f);
        sAT[lane * SP + n]        = (v0 - m) * inv * n1g[lane]      + n1b[lane];
        sAT[(lane + 32) * SP + n] = (v1 - m) * inv * n1g[lane + 32] + n1b[lane + 32];
        sAT[(lane + 64) * SP + n] = (v2 - m) * inv * n1g[lane + 64] + n1b[lane + 64];
    }
    __syncthreads();

    // ---- QKV GEMM: 3 tiles of 96 output cols ----
    const int c = lane;
    const int g8 = warp;
    for (int ct = 0; ct < 3; ct++) {
        for (int i = tid; i < 96 * 96; i += 256) {
            int cl = i / 96, k = i - cl * 96;
            sW[k * 97 + cl] = qkv_w[(ct * 96 + cl) * 96 + k];
        }
        float bi0 = qkv_b[ct * 96 + c];
        float bi1 = qkv_b[ct * 96 + c + 32];
        float bi2 = qkv_b[ct * 96 + c + 64];
        __syncthreads();

        u64 acc[4][3];
        #pragma unroll
        for (int j = 0; j < 4; j++) { acc[j][0] = acc[j][1] = acc[j][2] = 0ull; }
        const int np = (g8 == 0) ? 4 : 3;   // token pairs: g8, g8+8, g8+16, (24)

        for (int k = 0; k < 96; k++) {
            float b0 = sW[k * 97 + c], b1 = sW[k * 97 + c + 32], b2 = sW[k * 97 + c + 64];
            u64 B0 = pk2(b0, b0), B1 = pk2(b1, b1), B2 = pk2(b2, b2);
            const float* ar = &sAT[k * SP];
            #pragma unroll
            for (int j = 0; j < 3; j++) {
                u64 A = *(const u64*)&ar[2 * (g8 + j * 8)];
                fma2(acc[j][0], A, B0);
                fma2(acc[j][1], A, B1);
                fma2(acc[j][2], A, B2);
            }
            if (g8 == 0) {
                u64 A = *(const u64*)&ar[48];
                fma2(acc[3][0], A, B0);
                fma2(acc[3][1], A, B1);
                fma2(acc[3][2], A, B2);
            }
        }
        const float biases[3] = { bi0, bi1, bi2 };
        for (int j = 0; j < np; j++) {
            int tp = (j < 3) ? (g8 + j * 8) : 24;
            int n0 = 2 * tp;
            #pragma unroll
            for (int m = 0; m < 3; m++) {
                int col = c + m * 32;
                float lo, hi; up2(acc[j][m], lo, hi);
                lo += biases[m]; hi += biases[m];
                if (ct < 2) {
                    sQK[n0 * QKP + ct * 96 + col] = lo;
                    if (n0 + 1 < NN) sQK[(n0 + 1) * QKP + ct * 96 + col] = hi;
                } else {
                    *(float2*)&sVT[col * SP + n0] = make_float2(lo, hi);
                }
            }
        }
        __syncthreads();   // also: last read of sW before sS overwrites it
    }

    // ---- scores: QK^T * scale + bias + mask  (sS aliases sW) ----
    const float scale = 0.17677669529663689f;
    const float* maskw = attn_mask + (size_t)wi * NN * NN;
    for (int idx = tid; idx < NH * NN * NN; idx += 256) {
        int h = idx / (NN * NN);
        int r = idx - h * NN * NN;
        int i = r / NN, j = r - i * NN;
        const float* qp = &sQK[i * QKP + h * HD];
        const float* kp = &sQK[j * QKP + 96 + h * HD];
        u64 acc = 0ull;
        #pragma unroll
        for (int d = 0; d < 16; d++)
            fma2(acc, *(const u64*)&qp[2 * d], *(const u64*)&kp[2 * d]);
        float a0, a1; up2(acc, a0, a1);
        float s = (a0 + a1) * scale
                + rel_bias_table[rel_index[r] * NH + h]
                + maskw[r];
        sS[(h * NN + i) * SP + j] = s;
    }
    __syncthreads();

    // ---- softmax (warp per row) + zero pad col 49 ----
    for (int row = warp; row < NH * NN; row += 8) {
        float* rp = &sS[row * SP];
        float x0 = (lane < NN) ? rp[lane] : -1e30f;
        float x1 = (lane + 32 < NN) ? rp[lane + 32] : -1e30f;
        float mx = fmaxf(x0, x1);
        #pragma unroll
        for (int o = 16; o > 0; o >>= 1)
            mx = fmaxf(mx, __shfl_xor_sync(0xffffffffu, mx, o));
        float e0 = (lane < NN) ? __expf(x0 - mx) : 0.f;
        float e1 = (lane + 32 < NN) ? __expf(x1 - mx) : 0.f;
        float sum = e0 + e1;
        #pragma unroll
        for (int o = 16; o > 0; o >>= 1)
            sum += __shfl_xor_sync(0xffffffffu, sum, o);
        float inv = 1.0f / sum;
        if (lane < NN) rp[lane] = e0 * inv;
        if (lane + 32 < NN) rp[lane + 32] = e1 * inv;
        if (lane == 0) rp[49] = 0.f;
    }
    __syncthreads();

    // ---- attn @ V  -> sOT (aliases sAT) [col][tok] ----
    float* sOT = sAT;
    for (int idx = tid; idx < CC * NN; idx += 256) {
        int col = idx / NN, i = idx - col * NN;
        int h = col >> 5;
        const float* sp = &sS[(h * NN + i) * SP];
        const float* vp = &sVT[col * SP];
        u64 acc = 0ull;
        #pragma unroll
        for (int jp = 0; jp < 25; jp++)
            fma2(acc, *(const u64*)&sp[2 * jp], *(const u64*)&vp[2 * jp]);
        float a0, a1; up2(acc, a0, a1);
        sOT[col * SP + i] = a0 + a1;
    }
    __syncthreads();   // last read of sS before sW overwrites it

    // ---- proj (sW aliases sS, safe after sync) ----
    for (int i = tid; i < 96 * 96; i += 256) {
        int cl = i / 96, k = i - cl * 96;
        sW[k * 97 + cl] = proj_w[cl * 96 + k];
    }
    if (tid < 96) sOT[tid * SP + 49] = 0.f;
    float pb0 = proj_b[c];
    float pb1 = proj_b[c + 32];
    float pb2 = proj_b[c + 64];
    __syncthreads();

    u64 acc[4][3];
    #pragma unroll
    for (int j = 0; j < 4; j++) { acc[j][0] = acc[j][1] = acc[j][2] = 0ull; }
    const int np = (g8 == 0) ? 4 : 3;
    for (int k = 0; k < 96; k++) {
        float b0 = sW[k * 97 + c], b1 = sW[k * 97 + c + 32], b2 = sW[k * 97 + c + 64];
        u64 B0 = pk2(b0, b0), B1 = pk2(b1, b1), B2 = pk2(b2, b2);
        const float* ar = &sOT[k * SP];
        #pragma unroll
        for (int j = 0; j < 3; j++) {
            u64 A = *(const u64*)&ar[2 * (g8 + j * 8)];
            fma2(acc[j][0], A, B0);
            fma2(acc[j][1], A, B1);
            fma2(acc[j][2], A, B2);
        }
        if (g8 == 0) {
            u64 A = *(const u64*)&ar[48];
            fma2(acc[3][0], A, B0);
            fma2(acc[3][1], A, B1);
            fma2(acc[3][2], A, B2);
        }
    }
    const float pbs[3] = { pb0, pb1, pb2 };
    for (int j = 0; j < np; j++) {
        int tp = (j < 3) ? (g8 + j * 8) : 24;
        #pragma unroll
        for (int half = 0; half < 2; half++) {
            int n = 2 * tp + half;
            if (n >= NN) break;
            int r = n / WS, cc = n - r * WS;
            int sh = (wh * WS + r + SHIFT) % IMGH;
            int sw = (ww * WS + cc + SHIFT) % IMGW;
            size_t base = (size_t)((b * IMGH + sh) * IMGW + sw) * CC;
            #pragma unroll
            for (int m = 0; m < 3; m++) {
                int col = c + m * 32;
                float lo, hi; up2(acc[j][m], lo, hi);
                float v = half ? hi : lo;
                g_x1[base + col] = x[base + col] + v + pbs[m];
            }
        }
    }
}

// =====================================================================
// Kernel 2: LN2 + fc1 + GELU + fc2 + residual
// 32 tokens/CTA, 256 threads, 2 CTAs/SM
// =====================================================================
#define MTOK 32
#define TP 34                 // 32 tokens + 2 pad
#define XT_OFF 0              // sXT [96][34]   3264
#define HT_OFF 3264           // sHT [384][34]  13056
#define W2_OFF 16320          // sW  [96][97]   9312
#define SMEM2_FLOATS 25632    // 102528 B -> 2 CTAs/SM

__global__ void __launch_bounds__(256) k_mlp(
    const float* __restrict__ n2g, const float* __restrict__ n2b,
    const float* __restrict__ fc1_w, const float* __restrict__ fc1_b,
    const float* __restrict__ fc2_w, const float* __restrict__ fc2_b,
    float* __restrict__ out)
{
    extern __shared__ float sm[];
    float* sXT = sm + XT_OFF;
    float* sHT = sm + HT_OFF;
    float* sW  = sm + W2_OFF;

    const int tid = threadIdx.x;
    const int lane = tid & 31;
    const int warp = tid >> 5;
    const int t0 = blockIdx.x * MTOK;
    const int c = lane;
    const int g8 = warp;

    // LN2 -> sXT [ch][tok]
    for (int n = warp; n < MTOK; n += 8) {
        const float* xp = g_x1 + (size_t)(t0 + n) * CC;
        float v0 = xp[lane], v1 = xp[lane + 32], v2 = xp[lane + 64];
        float s = v0 + v1 + v2, s2 = v0 * v0 + v1 * v1 + v2 * v2;
        #pragma unroll
        for (int o = 16; o > 0; o >>= 1) {
            s  += __shfl_xor_sync(0xffffffffu, s, o);
            s2 += __shfl_xor_sync(0xffffffffu, s2, o);
        }
        float m = s * (1.0f / CC);
        float inv = rsqrtf(s2 * (1.0f / CC) - m * m + 1e-5f);
        sXT[lane * TP + n]        = (v0 - m) * inv * n2g[lane]      + n2b[lane];
        sXT[(lane + 32) * TP + n] = (v1 - m) * inv * n2g[lane + 32] + n2b[lane + 32];
        sXT[(lane + 64) * TP + n] = (v2 - m) * inv * n2g[lane + 64] + n2b[lane + 64];
    }
    __syncthreads();

    // fc1 + GELU: 4 tiles of 96 cols; 16 token pairs, 2 per warp
    for (int ct = 0; ct < 4; ct++) {
        for (int i = tid; i < 96 * 96; i += 256) {
            int cl = i / 96, k = i - cl * 96;
            sW[k * 97 + cl] = fc1_w[(ct * 96 + cl) * 96 + k];
        }
        float bi0 = fc1_b[ct * 96 + c];
        float bi1 = fc1_b[ct * 96 + c + 32];
        float bi2 = fc1_b[ct * 96 + c + 64];
        __syncthreads();

        u64 acc[2][3];
        #pragma unroll
        for (int j = 0; j < 2; j++) { acc[j][0] = acc[j][1] = acc[j][2] = 0ull; }
        for (int k = 0; k < 96; k++) {
            float b0 = sW[k * 97 + c], b1 = sW[k * 97 + c + 32], b2 = sW[k * 97 + c + 64];
            u64 B0 = pk2(b0, b0), B1 = pk2(b1, b1), B2 = pk2(b2, b2);
            const float* ar = &sXT[k * TP];
            #pragma unroll
            for (int j = 0; j < 2; j++) {
                u64 A = *(const u64*)&ar[2 * (g8 * 2 + j)];
                fma2(acc[j][0], A, B0);
                fma2(acc[j][1], A, B1);
                fma2(acc[j][2], A, B2);
            }
        }
        const float biases[3] = { bi0, bi1, bi2 };
        #pragma unroll
        for (int j = 0; j < 2; j++) {
            int n0 = 2 * (g8 * 2 + j);
            #pragma unroll
            for (int m = 0; m < 3; m++) {
                int col = ct * 96 + c + m * 32;
                float lo, hi; up2(acc[j][m], lo, hi);
                lo += biases[m]; hi += biases[m];
                lo = 0.5f * lo * (1.0f + erff(lo * 0.70710678118654752f));
                hi = 0.5f * hi * (1.0f + erff(hi * 0.70710678118654752f));
                *(float2*)&sHT[col * TP + n0] = make_float2(lo, hi);
            }
        }
        __syncthreads();
    }

    // fc2: 96 cols, k = 384 in 4 staged chunks of 96
    u64 acc[2][3];
    #pragma unroll
    for (int j = 0; j < 2; j++) { acc[j][0] = acc[j][1] = acc[j][2] = 0ull; }
    for (int kc = 0; kc < 4; kc++) {
        for (int i = tid; i < 96 * 96; i += 256) {
            int cl = i / 96, kk = i - cl * 96;
            sW[kk * 97 + cl] = fc2_w[cl * HID + kc * 96 + kk];
        }
        __syncthreads();
        for (int kk = 0; kk < 96; kk++) {
            float b0 = sW[kk * 97 + c], b1 = sW[kk * 97 + c + 32], b2 = sW[kk * 97 + c + 64];
            u64 B0 = pk2(b0, b0), B1 = pk2(b1, b1), B2 = pk2(b2, b2);
            const float* ar = &sHT[(kc * 96 + kk) * TP];
            #pragma unroll
            for (int j = 0; j < 2; j++) {
                u64 A = *(const u64*)&ar[2 * (g8 * 2 + j)];
                fma2(acc[j][0], A, B0);
                fma2(acc[j][1], A, B1);
                fma2(acc[j][2], A, B2);
            }
        }
        __syncthreads();
    }
    float fb0 = fc2_b[c], fb1 = fc2_b[c + 32], fb2 = fc2_b[c + 64];
    const float fbs[3] = { fb0, fb1, fb2 };
    #pragma unroll
    for (int j = 0; j < 2; j++) {
        int n0 = 2 * (g8 * 2 + j);
        size_t base0 = (size_t)(t0 + n0) * CC;
        size_t base1 = (size_t)(t0 + n0 + 1) * CC;
        #pragma unroll
        for (int m = 0; m < 3; m++) {
            int col = c + m * 32;
            float lo, hi; up2(acc[j][m], lo, hi);
            out[base0 + col] = g_x1[base0 + col] + lo + fbs[m];
            out[base1 + col] = g_x1[base1 + col] + hi + fbs[m];
        }
    }
}

// =====================================================================
extern "C" void kernel_launch(void* const* d_in, const int* in_sizes, int n_in,
                              void* d_out, int out_size)
{
    const float* x      = (const float*)d_in[0];
    const float* mask   = (const float*)d_in[1];
    const int*   relidx = (const int*)  d_in[2];
    const float* n1g    = (const float*)d_in[3];
    const float* n1b    = (const float*)d_in[4];
    const float* qkv_w  = (const float*)d_in[5];
    const float* qkv_b  = (const float*)d_in[6];
    const float* proj_w = (const float*)d_in[7];
    const float* proj_b = (const float*)d_in[8];
    const float* rbt    = (const float*)d_in[9];
    const float* n2g    = (const float*)d_in[10];
    const float* n2b    = (const float*)d_in[11];
    const float* fc1_w  = (const float*)d_in[12];
    const float* fc1_b  = (const float*)d_in[13];
    const float* fc2_w  = (const float*)d_in[14];
    const float* fc2_b  = (const float*)d_in[15];
    float* out = (float*)d_out;

    const int smem1 = SMEM1_FLOATS * 4;   // 113672 -> 2 CTAs/SM
    const int smem2 = SMEM2_FLOATS * 4;   // 102528 -> 2 CTAs/SM

    cudaFuncSetAttribute(k_attn_fused, cudaFuncAttributeMaxDynamicSharedMemorySize, smem1);
    cudaFuncSetAttribute(k_mlp,        cudaFuncAttributeMaxDynamicSharedMemorySize, smem2);

    k_attn_fused<<<NWIN, 256, smem1>>>(x, mask, relidx, rbt, n1g, n1b,
                                       qkv_w, qkv_b, proj_w, proj_b);
    k_mlp<<<TOK / MTOK, 256, smem2>>>(n2g, n2b, fc1_w, fc1_b, fc2_w, fc2_b, out);
}

// round 15
// speedup vs baseline: 2.3132x; 1.6733x over previous
#include <cuda_runtime.h>
#include <cuda_bf16.h>
#include <math.h>

#define BATCH 32
#define IMGH 112
#define IMGW 112
#define CC 96
#define NH 3
#define WS 7
#define SHIFT 3
#define NN 49
#define HD 32
#define NWIN 8192
#define TOK 401408
#define HID 384
#define QKVC 288

typedef unsigned long long u64;
typedef unsigned int u32;

__device__ __forceinline__ u64 pk2(float lo, float hi) {
    u64 r; asm("mov.b64 %0,{%1,%2};" : "=l"(r) : "f"(lo), "f"(hi)); return r;
}
__device__ __forceinline__ void up2(u64 v, float& a, float& b) {
    asm("mov.b64 {%0,%1},%2;" : "=f"(a), "=f"(b) : "l"(v));
}
__device__ __forceinline__ void fma2(u64& d, u64 a, u64 b) {
    asm("fma.rn.f32x2 %0,%1,%2,%3;" : "=l"(d) : "l"(a), "l"(b), "l"(d));
}

__device__ float g_x1[(size_t)TOK * CC];   // 154 MB residual scratch

// bf16 weight copies for the tensor-core MLP
__device__ __align__(16) __nv_bfloat16 g_w1[HID * CC];   // fc1: [384][96]
__device__ __align__(16) __nv_bfloat16 g_w2[CC * HID];   // fc2: [96][384]

// =====================================================================
// smem float offsets (fused attention kernel) — sW and sS ALIASED
// =====================================================================
#define AT_OFF   0            // sAT/sOT [96][50]   4800
#define QK_OFF   4800         // sQK [49][194]      9506
#define VT_OFF   14306        // sVT [96][50]       4800
#define WS_OFF   19106        // sW [96][97] / sS [3][49][50]  9312
#define SMEM1_FLOATS 28418    // 113672 B -> 2 CTAs/SM
#define QKP 194
#define SP 50

// =====================================================================
// Kernel 1: gather+LN1+QKV+attention+proj+residual (unchanged, passing)
// =====================================================================
__global__ void __launch_bounds__(256) k_attn_fused(
    const float* __restrict__ x,
    const float* __restrict__ attn_mask,
    const int*   __restrict__ rel_index,
    const float* __restrict__ rel_bias_table,
    const float* __restrict__ n1g, const float* __restrict__ n1b,
    const float* __restrict__ qkv_w, const float* __restrict__ qkv_b,
    const float* __restrict__ proj_w, const float* __restrict__ proj_b)
{
    extern __shared__ float sm[];
    float* sAT = sm + AT_OFF;
    float* sQK = sm + QK_OFF;
    float* sVT = sm + VT_OFF;
    float* sW  = sm + WS_OFF;
    float* sS  = sm + WS_OFF;

    const int widx = blockIdx.x;
    const int b  = widx >> 8;
    const int wi = widx & 255;
    const int wh = wi >> 4;
    const int ww = wi & 15;
    const int tid  = threadIdx.x;
    const int lane = tid & 31;
    const int warp = tid >> 5;

    if (tid < 96) sAT[tid * SP + 49] = 0.f;
    for (int n = warp; n < NN; n += 8) {
        int r = n / WS, cc = n - r * WS;
        int sh = (wh * WS + r + SHIFT) % IMGH;
        int sw = (ww * WS + cc + SHIFT) % IMGW;
        const float* xp = x + (size_t)((b * IMGH + sh) * IMGW + sw) * CC;
        float v0 = xp[lane], v1 = xp[lane + 32], v2 = xp[lane + 64];
        float s = v0 + v1 + v2, s2 = v0 * v0 + v1 * v1 + v2 * v2;
        #pragma unroll
        for (int o = 16; o > 0; o >>= 1) {
            s  += __shfl_xor_sync(0xffffffffu, s, o);
            s2 += __shfl_xor_sync(0xffffffffu, s2, o);
        }
        float m = s * (1.0f / CC);
        float inv = rsqrtf(s2 * (1.0f / CC) - m * m + 1e-5f);
        sAT[lane * SP + n]        = (v0 - m) * inv * n1g[lane]      + n1b[lane];
        sAT[(lane + 32) * SP + n] = (v1 - m) * inv * n1g[lane + 32] + n1b[lane + 32];
        sAT[(lane + 64) * SP + n] = (v2 - m) * inv * n1g[lane + 64] + n1b[lane + 64];
    }
    __syncthreads();

    const int c = lane;
    const int g8 = warp;
    for (int ct = 0; ct < 3; ct++) {
        for (int i = tid; i < 96 * 96; i += 256) {
            int cl = i / 96, k = i - cl * 96;
            sW[k * 97 + cl] = qkv_w[(ct * 96 + cl) * 96 + k];
        }
        float bi0 = qkv_b[ct * 96 + c];
        float bi1 = qkv_b[ct * 96 + c + 32];
        float bi2 = qkv_b[ct * 96 + c + 64];
        __syncthreads();

        u64 acc[4][3];
        #pragma unroll
        for (int j = 0; j < 4; j++) { acc[j][0] = acc[j][1] = acc[j][2] = 0ull; }
        const int np = (g8 == 0) ? 4 : 3;

        for (int k = 0; k < 96; k++) {
            float b0 = sW[k * 97 + c], b1 = sW[k * 97 + c + 32], b2 = sW[k * 97 + c + 64];
            u64 B0 = pk2(b0, b0), B1 = pk2(b1, b1), B2 = pk2(b2, b2);
            const float* ar = &sAT[k * SP];
            #pragma unroll
            for (int j = 0; j < 3; j++) {
                u64 A = *(const u64*)&ar[2 * (g8 + j * 8)];
                fma2(acc[j][0], A, B0);
                fma2(acc[j][1], A, B1);
                fma2(acc[j][2], A, B2);
            }
            if (g8 == 0) {
                u64 A = *(const u64*)&ar[48];
                fma2(acc[3][0], A, B0);
                fma2(acc[3][1], A, B1);
                fma2(acc[3][2], A, B2);
            }
        }
        const float biases[3] = { bi0, bi1, bi2 };
        for (int j = 0; j < np; j++) {
            int tp = (j < 3) ? (g8 + j * 8) : 24;
            int n0 = 2 * tp;
            #pragma unroll
            for (int m = 0; m < 3; m++) {
                int col = c + m * 32;
                float lo, hi; up2(acc[j][m], lo, hi);
                lo += biases[m]; hi += biases[m];
                if (ct < 2) {
                    sQK[n0 * QKP + ct * 96 + col] = lo;
                    if (n0 + 1 < NN) sQK[(n0 + 1) * QKP + ct * 96 + col] = hi;
                } else {
                    *(float2*)&sVT[col * SP + n0] = make_float2(lo, hi);
                }
            }
        }
        __syncthreads();
    }

    const float scale = 0.17677669529663689f;
    const float* maskw = attn_mask + (size_t)wi * NN * NN;
    for (int idx = tid; idx < NH * NN * NN; idx += 256) {
        int h = idx / (NN * NN);
        int r = idx - h * NN * NN;
        int i = r / NN, j = r - i * NN;
        const float* qp = &sQK[i * QKP + h * HD];
        const float* kp = &sQK[j * QKP + 96 + h * HD];
        u64 acc = 0ull;
        #pragma unroll
        for (int d = 0; d < 16; d++)
            fma2(acc, *(const u64*)&qp[2 * d], *(const u64*)&kp[2 * d]);
        float a0, a1; up2(acc, a0, a1);
        float s = (a0 + a1) * scale
                + rel_bias_table[rel_index[r] * NH + h]
                + maskw[r];
        sS[(h * NN + i) * SP + j] = s;
    }
    __syncthreads();

    for (int row = warp; row < NH * NN; row += 8) {
        float* rp = &sS[row * SP];
        float x0 = (lane < NN) ? rp[lane] : -1e30f;
        float x1 = (lane + 32 < NN) ? rp[lane + 32] : -1e30f;
        float mx = fmaxf(x0, x1);
        #pragma unroll
        for (int o = 16; o > 0; o >>= 1)
            mx = fmaxf(mx, __shfl_xor_sync(0xffffffffu, mx, o));
        float e0 = (lane < NN) ? __expf(x0 - mx) : 0.f;
        float e1 = (lane + 32 < NN) ? __expf(x1 - mx) : 0.f;
        float sum = e0 + e1;
        #pragma unroll
        for (int o = 16; o > 0; o >>= 1)
            sum += __shfl_xor_sync(0xffffffffu, sum, o);
        float inv = 1.0f / sum;
        if (lane < NN) rp[lane] = e0 * inv;
        if (lane + 32 < NN) rp[lane + 32] = e1 * inv;
        if (lane == 0) rp[49] = 0.f;
    }
    __syncthreads();

    float* sOT = sAT;
    for (int idx = tid; idx < CC * NN; idx += 256) {
        int col = idx / NN, i = idx - col * NN;
        int h = col >> 5;
        const float* sp = &sS[(h * NN + i) * SP];
        const float* vp = &sVT[col * SP];
        u64 acc = 0ull;
        #pragma unroll
        for (int jp = 0; jp < 25; jp++)
            fma2(acc, *(const u64*)&sp[2 * jp], *(const u64*)&vp[2 * jp]);
        float a0, a1; up2(acc, a0, a1);
        sOT[col * SP + i] = a0 + a1;
    }
    __syncthreads();

    for (int i = tid; i < 96 * 96; i += 256) {
        int cl = i / 96, k = i - cl * 96;
        sW[k * 97 + cl] = proj_w[cl * 96 + k];
    }
    if (tid < 96) sOT[tid * SP + 49] = 0.f;
    float pb0 = proj_b[c];
    float pb1 = proj_b[c + 32];
    float pb2 = proj_b[c + 64];
    __syncthreads();

    u64 acc[4][3];
    #pragma unroll
    for (int j = 0; j < 4; j++) { acc[j][0] = acc[j][1] = acc[j][2] = 0ull; }
    const int np = (g8 == 0) ? 4 : 3;
    for (int k = 0; k < 96; k++) {
        float b0 = sW[k * 97 + c], b1 = sW[k * 97 + c + 32], b2 = sW[k * 97 + c + 64];
        u64 B0 = pk2(b0, b0), B1 = pk2(b1, b1), B2 = pk2(b2, b2);
        const float* ar = &sOT[k * SP];
        #pragma unroll
        for (int j = 0; j < 3; j++) {
            u64 A = *(const u64*)&ar[2 * (g8 + j * 8)];
            fma2(acc[j][0], A, B0);
            fma2(acc[j][1], A, B1);
            fma2(acc[j][2], A, B2);
        }
        if (g8 == 0) {
            u64 A = *(const u64*)&ar[48];
            fma2(acc[3][0], A, B0);
            fma2(acc[3][1], A, B1);
            fma2(acc[3][2], A, B2);
        }
    }
    const float pbs[3] = { pb0, pb1, pb2 };
    for (int j = 0; j < np; j++) {
        int tp = (j < 3) ? (g8 + j * 8) : 24;
        #pragma unroll
        for (int half = 0; half < 2; half++) {
            int n = 2 * tp + half;
            if (n >= NN) break;
            int r = n / WS, cc = n - r * WS;
            int sh = (wh * WS + r + SHIFT) % IMGH;
            int sw = (ww * WS + cc + SHIFT) % IMGW;
            size_t base = (size_t)((b * IMGH + sh) * IMGW + sw) * CC;
            #pragma unroll
            for (int m = 0; m < 3; m++) {
                int col = c + m * 32;
                float lo, hi; up2(acc[j][m], lo, hi);
                float v = half ? hi : lo;
                g_x1[base + col] = x[base + col] + v + pbs[m];
            }
        }
    }
}

// =====================================================================
// Prep: fc1/fc2 weights -> bf16 row-major copies
// =====================================================================
__global__ void __launch_bounds__(256) k_prep(
    const float* __restrict__ fc1_w, const float* __restrict__ fc2_w)
{
    int idx = blockIdx.x * 256 + threadIdx.x;
    if (idx < HID * CC) {
        g_w1[idx] = __float2bfloat16_rn(fc1_w[idx]);
        g_w2[idx] = __float2bfloat16_rn(fc2_w[idx]);
    }
}

// =====================================================================
// Kernel 2: LN2 + fc1 + GELU + fc2 + residual — mma.sync bf16 HMMA
// 64 tokens/CTA, 256 threads (8 warps), 2 CTAs/SM
// smem: sX bf16 [64][104] @0 (13312 B)
//       sH bf16 [64][392] @13312 (50176 B)
//       sWs bf16 stage    @63488 (38400 B max)
// total 101888 B
// =====================================================================
#define MTOK 64
#define XP 104
#define HP 392
#define WP2 200
#define SMX_OFF 0
#define SMH_OFF 13312
#define SMW_OFF 63488
#define SMEM_MLP 101888

__device__ __forceinline__ void mma16816(
    float& c0, float& c1, float& c2, float& c3,
    u32 a0, u32 a1, u32 a2, u32 a3, u32 b0, u32 b1)
{
    asm volatile(
        "mma.sync.aligned.m16n8k16.row.col.f32.bf16.bf16.f32 "
        "{%0,%1,%2,%3},{%4,%5,%6,%7},{%8,%9},{%0,%1,%2,%3};"
        : "+f"(c0), "+f"(c1), "+f"(c2), "+f"(c3)
        : "r"(a0), "r"(a1), "r"(a2), "r"(a3), "r"(b0), "r"(b1));
}

__global__ void __launch_bounds__(256) k_mlp_mma(
    const float* __restrict__ n2g, const float* __restrict__ n2b,
    const float* __restrict__ fc1_b, const float* __restrict__ fc2_b,
    float* __restrict__ out)
{
    extern __shared__ char smem[];
    __nv_bfloat16* sX = (__nv_bfloat16*)(smem + SMX_OFF);
    __nv_bfloat16* sH = (__nv_bfloat16*)(smem + SMH_OFF);
    __nv_bfloat16* sWs = (__nv_bfloat16*)(smem + SMW_OFF);

    const int tid = threadIdx.x;
    const int lane = tid & 31;
    const int wid = tid >> 5;
    const int t0 = blockIdx.x * MTOK;

    const int g = lane >> 2;        // 0..7
    const int tig = lane & 3;       // 0..3
    const int mt = wid & 3;         // m-tile (16 rows)
    const int ns = (wid >> 2) * 48; // n-subrange within 96-chunk

    // ---- LN2 -> sX bf16 [64][104] ----
    for (int n = wid; n < MTOK; n += 8) {
        const float* xp = g_x1 + (size_t)(t0 + n) * CC;
        float v0 = xp[lane], v1 = xp[lane + 32], v2 = xp[lane + 64];
        float s = v0 + v1 + v2, s2 = v0 * v0 + v1 * v1 + v2 * v2;
        #pragma unroll
        for (int o = 16; o > 0; o >>= 1) {
            s  += __shfl_xor_sync(0xffffffffu, s, o);
            s2 += __shfl_xor_sync(0xffffffffu, s2, o);
        }
        float m = s * (1.0f / CC);
        float inv = rsqrtf(s2 * (1.0f / CC) - m * m + 1e-5f);
        sX[n * XP + lane]      = __float2bfloat16_rn((v0 - m) * inv * n2g[lane]      + n2b[lane]);
        sX[n * XP + lane + 32] = __float2bfloat16_rn((v1 - m) * inv * n2g[lane + 32] + n2b[lane + 32]);
        sX[n * XP + lane + 64] = __float2bfloat16_rn((v2 - m) * inv * n2g[lane + 64] + n2b[lane + 64]);
    }

    // ---- fc1 + GELU: 4 n-chunks of 96 ----
    for (int nc = 0; nc < 4; nc++) {
        __syncthreads();   // sWs free (prev chunk consumed / sX writes done)
        // stage fc1 weights rows [nc*96, nc*96+96) -> sWs [96][104]
        for (int i = tid; i < 96 * 12; i += 256) {
            int row = i / 12, part = i - row * 12;
            *(uint4*)((char*)sWs + row * 208 + part * 16) =
                *(const uint4*)((const char*)g_w1 + (nc * 96 + row) * 192 + part * 16);
        }
        __syncthreads();

        float acc[6][4];
        #pragma unroll
        for (int t = 0; t < 6; t++) { acc[t][0] = acc[t][1] = acc[t][2] = acc[t][3] = 0.f; }

        #pragma unroll
        for (int ks = 0; ks < 6; ks++) {
            int k0 = ks * 16;
            const __nv_bfloat16* ar = &sX[(mt * 16 + g) * XP + k0 + tig * 2];
            u32 a0 = *(const u32*)ar;
            u32 a1 = *(const u32*)(ar + 8 * XP);
            u32 a2 = *(const u32*)(ar + 8);
            u32 a3 = *(const u32*)(ar + 8 * XP + 8);
            #pragma unroll
            for (int t = 0; t < 6; t++) {
                const __nv_bfloat16* br = &sWs[(ns + t * 8 + g) * XP + k0 + tig * 2];
                u32 b0 = *(const u32*)br;
                u32 b1 = *(const u32*)(br + 8);
                mma16816(acc[t][0], acc[t][1], acc[t][2], acc[t][3], a0, a1, a2, a3, b0, b1);
            }
        }

        // epilogue: bias + exact GELU -> sH bf16
        #pragma unroll
        for (int t = 0; t < 6; t++) {
            int coll = ns + t * 8 + tig * 2;          // local col in chunk
            int col = nc * 96 + coll;                 // global hidden col
            float b0v = fc1_b[col], b1v = fc1_b[col + 1];
            float v0 = acc[t][0] + b0v, v1 = acc[t][1] + b1v;
            float v2 = acc[t][2] + b0v, v3 = acc[t][3] + b1v;
            v0 = 0.5f * v0 * (1.0f + erff(v0 * 0.70710678118654752f));
            v1 = 0.5f * v1 * (1.0f + erff(v1 * 0.70710678118654752f));
            v2 = 0.5f * v2 * (1.0f + erff(v2 * 0.70710678118654752f));
            v3 = 0.5f * v3 * (1.0f + erff(v3 * 0.70710678118654752f));
            __nv_bfloat162 lo = __floats2bfloat162_rn(v0, v1);
            __nv_bfloat162 hi = __floats2bfloat162_rn(v2, v3);
            *(u32*)&sH[(mt * 16 + g) * HP + col]     = *(u32*)&lo;
            *(u32*)&sH[(mt * 16 + g + 8) * HP + col] = *(u32*)&hi;
        }
    }

    // ---- fc2: 2 staged k-chunks of 192 ----
    float acc[6][4];
    #pragma unroll
    for (int t = 0; t < 6; t++) { acc[t][0] = acc[t][1] = acc[t][2] = acc[t][3] = 0.f; }

    for (int kc = 0; kc < 2; kc++) {
        __syncthreads();
        // stage fc2 weights [96][kc*192 .. +192) -> sWs [96][200]
        for (int i = tid; i < 96 * 24; i += 256) {
            int row = i / 24, part = i - row * 24;
            *(uint4*)((char*)sWs + row * 400 + part * 16) =
                *(const uint4*)((const char*)g_w2 + row * 768 + kc * 384 + part * 16);
        }
        __syncthreads();

        #pragma unroll
        for (int ks = 0; ks < 12; ks++) {
            int k0 = ks * 16;
            const __nv_bfloat16* ar = &sH[(mt * 16 + g) * HP + kc * 192 + k0 + tig * 2];
            u32 a0 = *(const u32*)ar;
            u32 a1 = *(const u32*)(ar + 8 * HP);
            u32 a2 = *(const u32*)(ar + 8);
            u32 a3 = *(const u32*)(ar + 8 * HP + 8);
            #pragma unroll
            for (int t = 0; t < 6; t++) {
                const __nv_bfloat16* br = &sWs[(ns + t * 8 + g) * WP2 + k0 + tig * 2];
                u32 b0 = *(const u32*)br;
                u32 b1 = *(const u32*)(br + 8);
                mma16816(acc[t][0], acc[t][1], acc[t][2], acc[t][3], a0, a1, a2, a3, b0, b1);
            }
        }
    }

    // ---- final epilogue: bias + residual -> out ----
    {
        int row0 = mt * 16 + g, row1 = row0 + 8;
        size_t base0 = (size_t)(t0 + row0) * CC;
        size_t base1 = (size_t)(t0 + row1) * CC;
        #pragma unroll
        for (int t = 0; t < 6; t++) {
            int col = ns + t * 8 + tig * 2;
            float b0v = fc2_b[col], b1v = fc2_b[col + 1];
            float2 x0 = *(const float2*)(g_x1 + base0 + col);
            float2 x1 = *(const float2*)(g_x1 + base1 + col);
            float2 o0, o1;
            o0.x = x0.x + acc[t][0] + b0v;
            o0.y = x0.y + acc[t][1] + b1v;
            o1.x = x1.x + acc[t][2] + b0v;
            o1.y = x1.y + acc[t][3] + b1v;
            *(float2*)(out + base0 + col) = o0;
            *(float2*)(out + base1 + col) = o1;
        }
    }
}

// =====================================================================
extern "C" void kernel_launch(void* const* d_in, const int* in_sizes, int n_in,
                              void* d_out, int out_size)
{
    const float* x      = (const float*)d_in[0];
    const float* mask   = (const float*)d_in[1];
    const int*   relidx = (const int*)  d_in[2];
    const float* n1g    = (const float*)d_in[3];
    const float* n1b    = (const float*)d_in[4];
    const float* qkv_w  = (const float*)d_in[5];
    const float* qkv_b  = (const float*)d_in[6];
    const float* proj_w = (const float*)d_in[7];
    const float* proj_b = (const float*)d_in[8];
    const float* rbt    = (const float*)d_in[9];
    const float* n2g    = (const float*)d_in[10];
    const float* n2b    = (const float*)d_in[11];
    const float* fc1_w  = (const float*)d_in[12];
    const float* fc1_b  = (const float*)d_in[13];
    const float* fc2_w  = (const float*)d_in[14];
    const float* fc2_b  = (const float*)d_in[15];
    float* out = (float*)d_out;

    const int smem1 = SMEM1_FLOATS * 4;   // 113672 -> 2 CTAs/SM

    cudaFuncSetAttribute(k_attn_fused, cudaFuncAttributeMaxDynamicSharedMemorySize, smem1);
    cudaFuncSetAttribute(k_mlp_mma,    cudaFuncAttributeMaxDynamicSharedMemorySize, SMEM_MLP);

    k_prep<<<(HID * CC + 255) / 256, 256>>>(fc1_w, fc2_w);
    k_attn_fused<<<NWIN, 256, smem1>>>(x, mask, relidx, rbt, n1g, n1b,
                                       qkv_w, qkv_b, proj_w, proj_b);
    k_mlp_mma<<<TOK / MTOK, 256, SMEM_MLP>>>(n2g, n2b, fc1_b, fc2_b, out);
}